// round 17
// baseline (speedup 1.0000x reference)
#include <cuda_runtime.h>
#include <cuda_fp16.h>
#include <cstdint>
#include <cstring>

#define B_   32
#define RES_ 56
#define C_   128
#define H_   4
#define HD_  32
#define WS_  7
#define NW_  8
#define NQ_  64
#define WA_  49
#define TOPK_ 64
#define KV_  128
#define P_   3136
#define M0_  (B_*P_)
#define M1_  (B_*NQ_)

__device__ __half g_qkv0[(size_t)M0_ * 384];
__device__ __half g_qkv1[(size_t)M1_ * 384];
__device__ __half g_rpb[(size_t)NQ_ * H_ * WA_ * KV_];
__device__ __half g_attn_out[(size_t)M0_ * C_];
__device__ __half g_x0h[(size_t)M0_ * C_];
__device__ __half g_x1h[(size_t)M1_ * C_];
__device__ __half g_wqkv[384 * 128];
__device__ __half g_wproj[128 * 128];

#define MMA_F16(C0,C1,C2,C3,A0,A1,A2,A3,B0,B1) \
    asm volatile("mma.sync.aligned.m16n8k16.row.col.f32.f16.f16.f32 " \
        "{%0,%1,%2,%3},{%4,%5,%6,%7},{%8,%9},{%0,%1,%2,%3};" \
        : "+f"(C0), "+f"(C1), "+f"(C2), "+f"(C3) \
        : "r"(A0), "r"(A1), "r"(A2), "r"(A3), "r"(B0), "r"(B1))

#define LDSM_X4(R0,R1,R2,R3,ADDR) \
    asm volatile("ldmatrix.sync.aligned.m8n8.x4.shared.b16 {%0,%1,%2,%3}, [%4];" \
        : "=r"(R0), "=r"(R1), "=r"(R2), "=r"(R3) : "r"(ADDR))

#define LDSM_X4_T(R0,R1,R2,R3,ADDR) \
    asm volatile("ldmatrix.sync.aligned.m8n8.x4.trans.shared.b16 {%0,%1,%2,%3}, [%4];" \
        : "=r"(R0), "=r"(R1), "=r"(R2), "=r"(R3) : "r"(ADDR))

#define CP16(DST, SRC) \
    asm volatile("cp.async.cg.shared.global [%0], [%1], 16;" :: "r"(DST), "l"(SRC))
#define CP_COMMIT() asm volatile("cp.async.commit_group;")
#define CP_WAIT1()  asm volatile("cp.async.wait_group 1;")
#define CP_WAIT0()  asm volatile("cp.async.wait_group 0;")

__device__ __forceinline__ uint32_t sh_addr(const void* p) {
    return (uint32_t)__cvta_generic_to_shared(p);
}
__device__ __forceinline__ uint32_t h2bits(float a, float b) {
    __half2 h = __floats2half2_rn(a, b);
    return *(uint32_t*)&h;
}

// ============================================================
// fused fp32 -> fp16 conversion over 4 segments
// ============================================================
__global__ void cvt_all(const float* __restrict__ s0, __half* __restrict__ d0, int n0,
                        const float* __restrict__ s1, __half* __restrict__ d1, int n1,
                        const float* __restrict__ s2, __half* __restrict__ d2, int n2,
                        const float* __restrict__ s3, __half* __restrict__ d3, int n3)
{
    const int total = n0 + n1 + n2 + n3;
    for (int i = blockIdx.x * blockDim.x + threadIdx.x; i < total;
         i += gridDim.x * blockDim.x) {
        const float* src; __half* dst; int k = i;
        if (k < n0)                { src = s0; dst = d0; }
        else if ((k -= n0) < n1)   { src = s1; dst = d1; }
        else if ((k -= n1) < n2)   { src = s2; dst = d2; }
        else { k -= n2;              src = s3; dst = d3; }
        float4 v = ((const float4*)src)[k];
        __half2 h0 = __floats2half2_rn(v.x, v.y);
        __half2 h1 = __floats2half2_rn(v.z, v.w);
        uint2 u = {*(uint32_t*)&h0, *(uint32_t*)&h1};
        ((uint2*)dst)[k] = u;
    }
}

// ============================================================
// all-fp16 GEMM with cp.async 2-stage pipeline
// ============================================================
template <typename TO>
__global__ __launch_bounds__(256) void gemm_h16(
    const __half* __restrict__ A, const __half* __restrict__ Bm,
    const float* __restrict__ bias, TO* __restrict__ C,
    int M, int N, int K)
{
    __shared__ __half As[2][128 * 40];
    __shared__ __half Bs[2][128 * 40];

    const int tid = threadIdx.x;
    const int m0 = blockIdx.x * 128;
    const int n0 = blockIdx.y * 128;
    const int warp = tid >> 5, lane = tid & 31;
    const int wm = (warp >> 2) * 64;
    const int wn = (warp & 3) * 32;
    const int r = lane >> 2;
    const int cI = lane & 3;

    const int a_row  = lane & 15;
    const int a_koff = (lane >> 4) * 8;
    const int b_row  = (lane & 7) + (lane >> 4) * 8;
    const int b_koff = ((lane >> 3) & 1) * 8;

    float c[4][4][4];
#pragma unroll
    for (int mt = 0; mt < 4; mt++)
#pragma unroll
        for (int nt = 0; nt < 4; nt++)
#pragma unroll
            for (int f = 0; f < 4; f++) c[mt][nt][f] = 0.f;

    const int lr = tid >> 1;
    const int ls = (tid & 1) * 16;
    const __half* Arow = A  + (size_t)(m0 + lr) * K + ls;
    const __half* Brow = Bm + (size_t)(n0 + lr) * K + ls;
    const uint32_t sa = sh_addr(&As[0][lr * 40 + ls]);
    const uint32_t sb = sh_addr(&Bs[0][lr * 40 + ls]);
    const uint32_t stageBytes = 128 * 40 * 2;

    const int NK = K >> 5;

    CP16(sa,      Arow);
    CP16(sa + 16, Arow + 8);
    CP16(sb,      Brow);
    CP16(sb + 16, Brow + 8);
    CP_COMMIT();

    for (int it = 0; it < NK; it++) {
        const int cur = it & 1;
        if (it + 1 < NK) {
            const int nxt = (it + 1) & 1;
            const int ko = (it + 1) << 5;
            CP16(sa + nxt * stageBytes,      Arow + ko);
            CP16(sa + nxt * stageBytes + 16, Arow + ko + 8);
            CP16(sb + nxt * stageBytes,      Brow + ko);
            CP16(sb + nxt * stageBytes + 16, Brow + ko + 8);
            CP_COMMIT();
            CP_WAIT1();
        } else {
            CP_WAIT0();
        }
        __syncthreads();

#pragma unroll
        for (int k16 = 0; k16 < 32; k16 += 16) {
            uint32_t a[4][4], b[4][2];
#pragma unroll
            for (int mt = 0; mt < 4; mt++) {
                uint32_t ad = sh_addr(&As[cur][(wm + mt * 16 + a_row) * 40 + k16 + a_koff]);
                LDSM_X4(a[mt][0], a[mt][1], a[mt][2], a[mt][3], ad);
            }
#pragma unroll
            for (int np = 0; np < 2; np++) {
                uint32_t ad = sh_addr(&Bs[cur][(wn + np * 16 + b_row) * 40 + k16 + b_koff]);
                LDSM_X4(b[2 * np][0], b[2 * np][1], b[2 * np + 1][0], b[2 * np + 1][1], ad);
            }
#pragma unroll
            for (int mt = 0; mt < 4; mt++)
#pragma unroll
                for (int nt = 0; nt < 4; nt++)
                    MMA_F16(c[mt][nt][0], c[mt][nt][1], c[mt][nt][2], c[mt][nt][3],
                            a[mt][0], a[mt][1], a[mt][2], a[mt][3],
                            b[nt][0], b[nt][1]);
        }
        __syncthreads();
    }

    if constexpr (sizeof(TO) == 4) {
#pragma unroll
        for (int mt = 0; mt < 4; mt++) {
            const int row = m0 + wm + mt * 16 + r;
#pragma unroll
            for (int nt = 0; nt < 4; nt++) {
                const int col = n0 + wn + nt * 8 + cI * 2;
                float2 bb = *(const float2*)&bias[col];
                float2 o0 = {c[mt][nt][0] + bb.x, c[mt][nt][1] + bb.y};
                float2 o1 = {c[mt][nt][2] + bb.x, c[mt][nt][3] + bb.y};
                *(float2*)&((float*)C)[(size_t)row * N + col]       = o0;
                *(float2*)&((float*)C)[(size_t)(row + 8) * N + col] = o1;
            }
        }
    } else {
        __half* Cs = (__half*)As;
#pragma unroll
        for (int mt = 0; mt < 4; mt++) {
            const int row = wm + mt * 16 + r;
#pragma unroll
            for (int nt = 0; nt < 4; nt++) {
                const int col = wn + nt * 8 + cI * 2;
                float2 bb = *(const float2*)&bias[n0 + col];
                *(uint32_t*)&Cs[row * 136 + col]       = h2bits(c[mt][nt][0] + bb.x, c[mt][nt][1] + bb.y);
                *(uint32_t*)&Cs[(row + 8) * 136 + col] = h2bits(c[mt][nt][2] + bb.x, c[mt][nt][3] + bb.y);
            }
        }
        __syncthreads();
#pragma unroll
        for (int it2 = 0; it2 < 8; it2++) {
            const int idx = tid + it2 * 256;
            const int row = idx >> 4, chunk = idx & 15;
            uint4 v = *(const uint4*)&Cs[row * 136 + chunk * 8];
            *(uint4*)&((__half*)C)[(size_t)(m0 + row) * N + n0 + chunk * 8] = v;
        }
    }
}

// ============================================================
// RPB MLP precompute -> fp16 table
// ============================================================
__global__ void rpb_kernel(
    const float* __restrict__ coords0, const float* __restrict__ coords1,
    const float* __restrict__ w1a, const float* __restrict__ b1a,
    const float* __restrict__ w2a, const float* __restrict__ b2a,
    const float* __restrict__ w1b, const float* __restrict__ b1b,
    const float* __restrict__ w2b, const float* __restrict__ b2b,
    __half* __restrict__ rpb)
{
    int t = blockIdx.x * blockDim.x + threadIdx.x;
    const int TOT = NQ_ * WA_ * KV_;
    if (t >= TOT) return;
    int j = t & 127;
    int i = (t >> 7) % WA_;
    int w = t / (KV_ * WA_);

    const float *co, *w1, *b1, *w2, *b2;
    int jj;
    if (j < TOPK_) { co = coords0; jj = j;          w1 = w1a; b1 = b1a; w2 = w2a; b2 = b2a; }
    else           { co = coords1; jj = j - TOPK_;  w1 = w1b; b1 = b1b; w2 = w2b; b2 = b2b; }

    size_t cbase = ((size_t)(w * WA_ + i) * TOPK_ + jj) * 2;
    float cy = co[cbase + 0];
    float cx = co[cbase + 1];

    float o0 = b2[0], o1 = b2[1], o2 = b2[2], o3 = b2[3];
#pragma unroll
    for (int tt = 0; tt < HD_; tt++) {
        float hsum = fmaxf(fmaf(w1[tt * 2], cy, fmaf(w1[tt * 2 + 1], cx, b1[tt])), 0.f);
        o0 = fmaf(w2[0 * HD_ + tt], hsum, o0);
        o1 = fmaf(w2[1 * HD_ + tt], hsum, o1);
        o2 = fmaf(w2[2 * HD_ + tt], hsum, o2);
        o3 = fmaf(w2[3 * HD_ + tt], hsum, o3);
    }
    size_t base = ((size_t)(w * H_) * WA_ + i) * KV_ + j;
    const size_t hstride = (size_t)WA_ * KV_;
    rpb[base + 0 * hstride] = __float2half(o0);
    rpb[base + 1 * hstride] = __float2half(o1);
    rpb[base + 2 * hstride] = __float2half(o2);
    rpb[base + 3 * hstride] = __float2half(o3);
}

// ============================================================
// FP16 attention, smem 36896 B, 6 CTAs/SM target
// ============================================================
#define SMEM_ATTN 36896

__global__ __launch_bounds__(256, 6) void attn_mma(
    const int* __restrict__ idx0, const int* __restrict__ idx1,
    const __half* __restrict__ rpb,
    const __half* __restrict__ qkv0, const __half* __restrict__ qkv1,
    __half* __restrict__ attn_out)
{
    extern __shared__ char smem_raw[];
    __half* k_s   = (__half*)(smem_raw);
    __half* v_s   = (__half*)(smem_raw);
    __half* out_s = (__half*)(smem_raw);
    float*  p_s   = (float*) (smem_raw + 10240);
    __half* q_s   = (__half*)(smem_raw + 10240);
    float*  inv_s = (float*) (smem_raw + 36640);
    char*   p_base = smem_raw + 10240;

    const int w = blockIdx.x, b = blockIdx.y, h = blockIdx.z;
    const int tid = threadIdx.x;
    const int warp = tid >> 5, lane = tid & 31;
    const int r = lane >> 2, cI = lane & 3;

    const int a_row  = lane & 15;
    const int a_koff = (lane >> 4) * 8;
    const int b_row  = (lane & 7) + (lane >> 4) * 8;
    const int b_koff = ((lane >> 3) & 1) * 8;

    // ---- gather K: 2 threads per key row ----
    const int j = tid >> 1;
    const int half16 = (tid & 1) * 16;
    const __half* basep;
    if (j < TOPK_) basep = qkv0 + ((size_t)b * P_ + idx0[w * TOPK_ + j]) * 384;
    else           basep = qkv1 + ((size_t)b * NQ_ + idx1[w * TOPK_ + (j - TOPK_)]) * 384;

    {
        const uint4* kp = (const uint4*)(basep + C_ + h * HD_ + half16);
        uint4 k0 = kp[0], k1 = kp[1];
        *(uint4*)&k_s[j * 40 + half16]     = k0;
        *(uint4*)&k_s[j * 40 + half16 + 8] = k1;
    }

    // ---- load Q (49 rows, pad to 64) ----
    const int wy = w >> 3, wx = w & 7;
    {
        int i = tid >> 2, d = (tid & 3) * 8;
        uint4 val = {0u, 0u, 0u, 0u};
        if (i < WA_) {
            int pos = (wy * WS_ + i / WS_) * RES_ + wx * WS_ + i % WS_;
            val = *(const uint4*)(qkv0 + ((size_t)b * P_ + pos) * 384 + h * HD_ + d);
        }
        *(uint4*)&q_s[i * 40 + d] = val;
    }
    __syncthreads();

    // ---- QK: M=64 N=128 K=32 ----
    float cq[2][4][4];
    {
        const int wm = (warp & 1) * 32, wn = (warp >> 1) * 32;
#pragma unroll
        for (int mt = 0; mt < 2; mt++)
#pragma unroll
            for (int nt = 0; nt < 4; nt++)
#pragma unroll
                for (int f = 0; f < 4; f++) cq[mt][nt][f] = 0.f;

#pragma unroll
        for (int k16 = 0; k16 < 32; k16 += 16) {
            uint32_t a[2][4], bb[4][2];
#pragma unroll
            for (int mt = 0; mt < 2; mt++) {
                uint32_t ad = sh_addr(&q_s[(wm + mt * 16 + a_row) * 40 + k16 + a_koff]);
                LDSM_X4(a[mt][0], a[mt][1], a[mt][2], a[mt][3], ad);
            }
#pragma unroll
            for (int np = 0; np < 2; np++) {
                uint32_t ad = sh_addr(&k_s[(wn + np * 16 + b_row) * 40 + k16 + b_koff]);
                LDSM_X4(bb[2 * np][0], bb[2 * np][1], bb[2 * np + 1][0], bb[2 * np + 1][1], ad);
            }
#pragma unroll
            for (int mt = 0; mt < 2; mt++)
#pragma unroll
                for (int nt = 0; nt < 4; nt++)
                    MMA_F16(cq[mt][nt][0], cq[mt][nt][1], cq[mt][nt][2], cq[mt][nt][3],
                            a[mt][0], a[mt][1], a[mt][2], a[mt][3],
                            bb[nt][0], bb[nt][1]);
        }
    }

    // ---- issue V gather loads ----
    uint4 vu0, vu1;
    {
        const uint4* vp = (const uint4*)(basep + 2 * C_ + h * HD_ + half16);
        vu0 = vp[0]; vu1 = vp[1];
    }
    __syncthreads();   // k_s, q_s dead

    // ---- epilogue: raw logits -> p_s; V rows -> v_s; zero the zero-row ----
    {
        const int wm = (warp & 1) * 32, wn = (warp >> 1) * 32;
#pragma unroll
        for (int mt = 0; mt < 2; mt++) {
            const int row0 = wm + mt * 16 + r;
            const int row1 = row0 + 8;
#pragma unroll
            for (int nt = 0; nt < 4; nt++) {
                const int col = wn + nt * 8 + cI * 2;
                if (row0 < WA_) {
                    float2 o = {cq[mt][nt][0], cq[mt][nt][1]};
                    *(float2*)&p_s[row0 * 132 + col] = o;
                }
                if (row1 < WA_) {
                    float2 o = {cq[mt][nt][2], cq[mt][nt][3]};
                    *(float2*)&p_s[row1 * 132 + col] = o;
                }
            }
        }
        if (tid < 132) *(uint32_t*)(p_base + WA_ * 528 + tid * 4) = 0u;

        *(uint4*)&v_s[j * 40 + half16]     = vu0;
        *(uint4*)&v_s[j * 40 + half16 + 8] = vu1;
    }
    __syncthreads();

    // ---- softmax (coalesced fp16 rpb, vectorized) ----
    const float scale = 0.17677669529663687f;
    const __half* rpb_wh = rpb + (size_t)(w * H_ + h) * WA_ * KV_;
    for (int i = warp; i < WA_; i += 8) {
        const __half* rrow = rpb_wh + i * KV_;
        float2 ra = __half22float2(*(const __half2*)&rrow[2 * lane]);
        float2 rb = __half22float2(*(const __half2*)&rrow[64 + 2 * lane]);
        float2 L0 = *(const float2*)&p_s[i * 132 + 2 * lane];
        float2 L1 = *(const float2*)&p_s[i * 132 + 64 + 2 * lane];
        float x0 = fmaf(L0.x, scale, ra.x);
        float x1 = fmaf(L0.y, scale, ra.y);
        float x2 = fmaf(L1.x, scale, rb.x);
        float x3 = fmaf(L1.y, scale, rb.y);
        float m = fmaxf(fmaxf(x0, x1), fmaxf(x2, x3));
#pragma unroll
        for (int off = 16; off; off >>= 1) m = fmaxf(m, __shfl_xor_sync(0xffffffffu, m, off));
        float e0 = __expf(x0 - m), e1 = __expf(x1 - m);
        float e2 = __expf(x2 - m), e3 = __expf(x3 - m);
        float s = e0 + e1 + e2 + e3;
#pragma unroll
        for (int off = 16; off; off >>= 1) s += __shfl_xor_sync(0xffffffffu, s, off);
        __half* ph = (__half*)(p_base + i * 528);
        *(uint32_t*)&ph[2 * lane]      = h2bits(e0, e1);
        *(uint32_t*)&ph[64 + 2 * lane] = h2bits(e2, e3);
        if (lane == 0) inv_s[i] = 1.f / s;
    }
    __syncthreads();

    // ---- PV: M=64 N=32 K=128; A rows >= WA_ remap to zero row ----
    {
        const int wm = (warp >> 1) * 16, wn = (warp & 1) * 16;
        const int vg = lane >> 3, vi = lane & 7;
        int row_a = wm + a_row;
        if (row_a >= WA_) row_a = WA_;
        const char* pa = p_base + row_a * 528;
        float c[2][4];
#pragma unroll
        for (int nt = 0; nt < 2; nt++)
#pragma unroll
            for (int f = 0; f < 4; f++) c[nt][f] = 0.f;

#pragma unroll
        for (int k16 = 0; k16 < KV_; k16 += 16) {
            uint32_t a0, a1, a2, a3;
            {
                uint32_t ad = sh_addr(pa + (k16 + a_koff) * 2);
                LDSM_X4(a0, a1, a2, a3, ad);
            }
            uint32_t bfr[2][2];
            {
                uint32_t ad = sh_addr(&v_s[(k16 + (vg & 1) * 8 + vi) * 40 + wn + (vg >> 1) * 8]);
                LDSM_X4_T(bfr[0][0], bfr[0][1], bfr[1][0], bfr[1][1], ad);
            }
#pragma unroll
            for (int nt = 0; nt < 2; nt++)
                MMA_F16(c[nt][0], c[nt][1], c[nt][2], c[nt][3],
                        a0, a1, a2, a3, bfr[nt][0], bfr[nt][1]);
        }

        __syncthreads();   // v_s reads done; reuse region as out_s

        const int row0 = wm + r, row1 = wm + r + 8;
#pragma unroll
        for (int nt = 0; nt < 2; nt++) {
            const int col = wn + nt * 8 + cI * 2;
            if (row0 < WA_) {
                float inv = inv_s[row0];
                *(uint32_t*)&out_s[row0 * 40 + col] = h2bits(c[nt][0] * inv, c[nt][1] * inv);
            }
            if (row1 < WA_) {
                float inv = inv_s[row1];
                *(uint32_t*)&out_s[row1 * 40 + col] = h2bits(c[nt][2] * inv, c[nt][3] * inv);
            }
        }
    }
    __syncthreads();

    // ---- coalesced output ----
    if (tid < WA_ * 4) {
        const int row = tid >> 2, chunk = tid & 3;
        uint4 v = *(const uint4*)&out_s[row * 40 + chunk * 8];
        *(uint4*)&attn_out[(((size_t)(b * NQ_ + w) * WA_) + row) * C_ + h * HD_ + chunk * 8] = v;
    }
}

// ============================================================
// launch
// ============================================================
extern "C" void kernel_launch(void* const* d_in, const int* in_sizes, int n_in,
                              void* d_out, int out_size)
{
    const float* x0      = (const float*)d_in[0];
    const float* x1      = (const float*)d_in[1];
    const float* qkv_w   = (const float*)d_in[2];
    const float* qkv_b   = (const float*)d_in[3];
    const float* proj_w  = (const float*)d_in[4];
    const float* proj_b  = (const float*)d_in[5];
    const float* rpb0_w1 = (const float*)d_in[6];
    const float* rpb0_b1 = (const float*)d_in[7];
    const float* rpb0_w2 = (const float*)d_in[8];
    const float* rpb0_b2 = (const float*)d_in[9];
    const float* rpb1_w1 = (const float*)d_in[10];
    const float* rpb1_b1 = (const float*)d_in[11];
    const float* rpb1_w2 = (const float*)d_in[12];
    const float* rpb1_b2 = (const float*)d_in[13];
    const float* coords0 = (const float*)d_in[14];
    const float* coords1 = (const float*)d_in[15];
    const int*   idx0    = (const int*)d_in[16];
    const int*   idx1    = (const int*)d_in[17];
    float* out = (float*)d_out;

    __half *qkv0, *qkv1, *rpb, *attn_out, *x0h, *x1h, *wqkv, *wproj;
    cudaGetSymbolAddress((void**)&qkv0, g_qkv0);
    cudaGetSymbolAddress((void**)&qkv1, g_qkv1);
    cudaGetSymbolAddress((void**)&rpb, g_rpb);
    cudaGetSymbolAddress((void**)&attn_out, g_attn_out);
    cudaGetSymbolAddress((void**)&x0h, g_x0h);
    cudaGetSymbolAddress((void**)&x1h, g_x1h);
    cudaGetSymbolAddress((void**)&wqkv, g_wqkv);
    cudaGetSymbolAddress((void**)&wproj, g_wproj);

    cudaFuncSetAttribute(attn_mma, cudaFuncAttributeMaxDynamicSharedMemorySize, SMEM_ATTN);

    cvt_all<<<640, 256>>>(x0, x0h, (int)((size_t)M0_ * C_ / 4),
                          x1, x1h, M1_ * C_ / 4,
                          qkv_w, wqkv, 384 * 128 / 4,
                          proj_w, wproj, 128 * 128 / 4);

    gemm_h16<__half><<<dim3(M0_ / 128, 384 / 128), 256>>>(x0h, wqkv, qkv_b, qkv0, M0_, 384, 128);
    gemm_h16<__half><<<dim3(M1_ / 128, 384 / 128), 256>>>(x1h, wqkv, qkv_b, qkv1, M1_, 384, 128);
    rpb_kernel<<<(NQ_ * WA_ * KV_ + 255) / 256, 256>>>(
        coords0, coords1,
        rpb0_w1, rpb0_b1, rpb0_w2, rpb0_b2,
        rpb1_w1, rpb1_b1, rpb1_w2, rpb1_b2, rpb);
    attn_mma<<<dim3(NQ_, B_, H_), 256, SMEM_ATTN>>>(idx0, idx1, rpb, qkv0, qkv1, attn_out);
    gemm_h16<float><<<dim3(M0_ / 128, C_ / 128), 256>>>(attn_out, wproj, proj_b, out, M0_, C_, 128);
}